// round 16
// baseline (speedup 1.0000x reference)
#include <cuda_runtime.h>
#include <cuda_bf16.h>
#include <cstdint>

// BiLSTM-CRF forward, all fp32 (Viterbi argmax stability forbids low precision).
// R15: recurrence split into 2 blocks per (dir,h-tile) across b-halves ->
// 256 blocks, 2 co-resident per SM (32KB smem, <=128 regs). One block's compute
// hides the other's barrier/L2/reduction stalls. XOR-swizzled conflict-free
// reduction. Inner loop = R11's proven 8x-reuse ldca/ldcg GEMV.
//
// Shapes: V=50000 E=512 H=512 HD=1024 B=64 L=512 T=16, START=14 STOP=15

#define NEGV -10000.0f

typedef unsigned long long u64;

// ---------------- scratch (__device__ globals) ----------------------------
__device__ float g_G[(size_t)32768 * 4096];       // input-proj gates [l*64+b][dir*2048+g*512+h]
__device__ float g_Wt[(size_t)512 * 4096];        // Wih^T combined  [k][n]
__device__ float g_Whi[2][(size_t)64 * 512 * 32]; // Whh interleaved [dir][ht][k][hp][g][ci]
__device__ float g_h[2][2][512][64];              // [parity][dir][k][b]
__device__ float g_hrow[(size_t)32768 * 1024];    // [l*64+b][dir*512+h]
__device__ float g_feats[(size_t)64 * 512 * 16];  // [b][l][t]
__device__ unsigned g_bar[2];                     // per-dir step barrier

// ---------------- helpers ---------------------------------------------------
__device__ __forceinline__ void ffma2(u64 &d, u64 a, u64 b) {
    asm("fma.rn.f32x2 %0, %1, %2, %0;" : "+l"(d) : "l"(a), "l"(b));
}
__device__ __forceinline__ u64 addf2(u64 a, u64 b) {
    u64 r; asm("add.rn.f32x2 %0, %1, %2;" : "=l"(r) : "l"(a), "l"(b)); return r;
}
__device__ __forceinline__ u64 pack2(float x) {
    u64 r; asm("mov.b64 %0, {%1, %1};" : "=l"(r) : "f"(x)); return r;
}
__device__ __forceinline__ float2 unpack2(u64 v) {
    float2 f; asm("mov.b64 {%0, %1}, %2;" : "=f"(f.x), "=f"(f.y) : "l"(v)); return f;
}
__device__ __forceinline__ float sigf(float x) { return 1.0f / (1.0f + expf(-x)); }
__device__ __forceinline__ void cp16(unsigned dst_sm, const float* src) {
    asm volatile("cp.async.cg.shared.global [%0], [%1], 16;\n" :: "r"(dst_sm), "l"(src));
}
template <int N> __device__ __forceinline__ void cp_wait() {
    asm volatile("cp.async.wait_group %0;\n" :: "n"(N) : "memory");
}
__device__ __forceinline__ void cp_commit() {
    asm volatile("cp.async.commit_group;\n" ::: "memory");
}
__device__ __forceinline__ void bar_arrive(unsigned* p) {
    asm volatile("red.release.gpu.global.add.u32 [%0], %1;" :: "l"(p), "r"(1u) : "memory");
}
__device__ __forceinline__ unsigned ld_acq(const unsigned* p) {
    unsigned v; asm volatile("ld.acquire.gpu.global.u32 %0, [%1];" : "=r"(v) : "l"(p) : "memory");
    return v;
}

// ---------------- prep kernels ---------------------------------------------
__global__ void prepA(const float* __restrict__ wf, const float* __restrict__ wb,
                      const float* __restrict__ h0) {
    int idx = blockIdx.x * 256 + threadIdx.x;
    if (idx < 2) g_bar[idx] = 0;
    if (idx < 2097152) {                       // 512*4096
        int k = idx >> 12, n = idx & 4095;
        g_Wt[idx] = (n < 2048) ? wf[n * 512 + k] : wb[(n - 2048) * 512 + k];
    } else {
        int r2 = idx - 2097152;                // 2*512*64: h0 -> [k][b]
        if (r2 < 65536) {
            int dir = r2 >> 15; int r = r2 & 32767;
            int k = r >> 6, b = r & 63;
            g_h[0][dir][k][b] = h0[((size_t)dir * 64 + b) * 512 + k];
        }
    }
}
// Whh re-layout: [dir][ht][k][hp][g][ci], rows of 32 floats per (ht,k)
__global__ void prepB(const float* __restrict__ whf, const float* __restrict__ whb) {
    int idx = blockIdx.x * 256 + threadIdx.x;  // 2*64*512*32
    int dir = idx >> 20; int r = idx & ((1 << 20) - 1);
    int ht = r >> 14; int r2 = r & 16383;
    int k = r2 >> 5;  int c = r2 & 31;
    int hpq = c >> 3, g = (c >> 1) & 3, ci = c & 1;
    int n = g * 512 + ht * 8 + hpq * 2 + ci;
    const float* w = dir ? whb : whf;
    g_Whi[dir][r] = w[(size_t)n * 512 + k];
}

// ---------------- input projection GEMM (cp.async 2-stage, proven) ----------
__global__ void __launch_bounds__(256) gemm1(const int* __restrict__ sent,
                                             const float* __restrict__ embed,
                                             const float* __restrict__ bf,
                                             const float* __restrict__ bb) {
    __shared__ float As[2][128][16];
    __shared__ float Bs[2][16][128];
    __shared__ int toks[128];
    int tid = threadIdx.x;
    int n0 = blockIdx.x * 128;
    int m0 = blockIdx.y * 128;
    if (tid < 128) { int m = m0 + tid; toks[tid] = sent[(m & 63) * 512 + (m >> 6)]; }
    __syncthreads();
    int tx = tid & 15, ty = tid >> 4;
    unsigned smA = (unsigned)__cvta_generic_to_shared(&As[0][0][0]);
    unsigned smB = (unsigned)__cvta_generic_to_shared(&Bs[0][0][0]);

    u64 acc[8][4];
#pragma unroll
    for (int i = 0; i < 8; i++)
#pragma unroll
        for (int j = 0; j < 4; j++) acc[i][j] = 0ull;

    auto issue = [&](int k0, int buf) {
#pragma unroll
        for (int r = 0; r < 2; r++) {
            int idx = tid * 2 + r;
            int am = idx >> 2, aq = idx & 3;
            cp16(smA + (unsigned)(((buf * 128 + am) * 16 + aq * 4) * 4),
                 embed + (size_t)toks[am] * 512 + k0 + aq * 4);
            int bk = idx >> 5, bn = idx & 31;
            cp16(smB + (unsigned)(((buf * 16 + bk) * 128 + bn * 4) * 4),
                 g_Wt + (size_t)(k0 + bk) * 4096 + n0 + bn * 4);
        }
        cp_commit();
    };

    issue(0, 0);
    for (int c = 0; c < 32; c++) {
        cp_wait<0>();
        __syncthreads();
        if (c < 31) issue((c + 1) * 16, (c + 1) & 1);
        const int buf = c & 1;
#pragma unroll
        for (int k = 0; k < 16; k++) {
            u64 bv[4];
#pragma unroll
            for (int j = 0; j < 4; j++)
                bv[j] = *(const u64*)&Bs[buf][k][(j * 16 + tx) * 2];
#pragma unroll
            for (int i = 0; i < 8; i++) {
                u64 av = pack2(As[buf][ty * 8 + i][k]);
#pragma unroll
                for (int j = 0; j < 4; j++) ffma2(acc[i][j], av, bv[j]);
            }
        }
    }
#pragma unroll
    for (int j = 0; j < 4; j++) {
        int n = n0 + (j * 16 + tx) * 2;
        float2 bias;
        bias.x = (n < 2048) ? bf[n] : bb[n - 2048];
        bias.y = (n + 1 < 2048) ? bf[n + 1] : bb[n + 1 - 2048];
#pragma unroll
        for (int i = 0; i < 8; i++) {
            float2 v = unpack2(acc[i][j]);
            size_t row = (size_t)(m0 + ty * 8 + i);
            *(float2*)&g_G[row * 4096 + n] = make_float2(v.x + bias.x, v.y + bias.y);
        }
    }
}

// ---------------- persistent LSTM recurrence --------------------------------
// 256 blocks = 2 dirs x 64 h-tiles x 2 b-halves; 2 blocks co-resident per SM.
// 256 threads = 8 warps; warp = k-eighth; lane = (bg 0..7, hp 0..3);
// thread = 4 b x 1 h-pair over 64 k. Swizzled conflict-free reduction.
__global__ void __launch_bounds__(256, 2) lstm_persist(
        const float* __restrict__ c0) {
    __shared__ ulonglong2 red[2048];           // 32KB
    const int tid  = threadIdx.x;
    const int lane = tid & 31;
    const int kq   = tid >> 5;        // k-eighth 0..7
    const int bg   = lane >> 2;       // 0..7 (b-group of 4 within half)
    const int hp   = lane & 3;        // 0..3 (h-pair)
    const int bhf  = blockIdx.x & 1;  // b-half
    const int ht   = (blockIdx.x >> 1) & 63;
    const int dir  = blockIdx.x >> 7;
    const int h0   = ht * 8;
    const int ob   = tid >> 2, ohp = tid & 3;  // owner cell (tid<128): ob in [0,32)
    const int bglo = bhf * 32;                 // global b offset of this half

    // publish atom indices (swizzled): atom(c,kq) = c*8 + (kq ^ key), 
    // c = (bg*4+bs)*8 + hp*2 + gp, key = ((bs&1)<<2)|hp
    int watom[4][2];
#pragma unroll
    for (int bs = 0; bs < 4; bs++) {
        int key = ((bs & 1) << 2) | hp;
#pragma unroll
        for (int gp = 0; gp < 2; gp++)
            watom[bs][gp] = ((bg * 4 + bs) * 8 + hp * 2 + gp) * 8 + (kq ^ key);
    }
    const int rkey = ((ob & 1) << 2) | ohp;    // owner read key

    const float* Wh = g_Whi[dir] + ((size_t)ht * 512 + kq * 64) * 32 + hp * 8;

    float2 creg = make_float2(0.f, 0.f);
    if (tid < 128)
        creg = *(const float2*)&c0[((size_t)dir * 64 + bglo + ob) * 512 + h0 + 2 * ohp];

    for (int t = 0; t < 512; t++) {
        const int p = t & 1;
        const int l = dir ? (511 - t) : t;

        // owners: G prefetch into registers (consumed post-reduction)
        float2 gpre[4];
        if (tid < 128) {
            const float* Gp = g_G + ((size_t)l * 64 + bglo + ob) * 4096
                            + (size_t)dir * 2048 + h0 + 2 * ohp;
#pragma unroll
            for (int g = 0; g < 4; g++) gpre[g] = __ldcg((const float2*)(Gp + g * 512));
        }

        // ---- GEMV over (k-eighth, 4 b) slice ----
        const float* Ab = &g_h[p][dir][kq * 64][bglo + bg * 4];  // row stride 64
        u64 acc[4][4];
#pragma unroll
        for (int b = 0; b < 4; b++)
#pragma unroll
            for (int g = 0; g < 4; g++) acc[b][g] = 0ull;

        float4 ring[4];
#pragma unroll
        for (int i = 0; i < 4; i++) ring[i] = __ldcg((const float4*)(Ab + i * 64));

#pragma unroll 4
        for (int kk = 0; kk < 64; kk++) {
            float4 ha = ring[kk & 3];
            if (kk + 4 < 64)
                ring[kk & 3] = __ldcg((const float4*)(Ab + (kk + 4) * 64));
            const ulonglong2* wrow = (const ulonglong2*)(Wh + kk * 32);
            ulonglong2 wA = __ldca(wrow);       // gates i,f (h-pair packed)
            ulonglong2 wB = __ldca(wrow + 1);   // gates g,o
            float hs[4] = {ha.x, ha.y, ha.z, ha.w};
#pragma unroll
            for (int b = 0; b < 4; b++) {
                u64 a = pack2(hs[b]);
                ffma2(acc[b][0], a, wA.x);
                ffma2(acc[b][1], a, wA.y);
                ffma2(acc[b][2], a, wB.x);
                ffma2(acc[b][3], a, wB.y);
            }
        }

        // ---- publish partials (swizzled) ----
#pragma unroll
        for (int bs = 0; bs < 4; bs++) {
            red[watom[bs][0]] = make_ulonglong2(acc[bs][0], acc[bs][1]);
            red[watom[bs][1]] = make_ulonglong2(acc[bs][2], acc[bs][3]);
        }
        __syncthreads();

        // ---- owners: reduce 8 k-eighths + fused LSTM pointwise ----
        if (tid < 128) {
            const int c0a = (ob * 8 + ohp * 2) * 8;
            u64 s0 = 0ull, s1 = 0ull, s2 = 0ull, s3 = 0ull;
#pragma unroll
            for (int k8 = 0; k8 < 8; k8++) {
                ulonglong2 q0 = red[c0a + (k8 ^ rkey)];
                ulonglong2 q1 = red[c0a + 8 + (k8 ^ rkey)];
                s0 = addf2(s0, q0.x); s1 = addf2(s1, q0.y);
                s2 = addf2(s2, q1.x); s3 = addf2(s3, q1.y);
            }
            float2 si = unpack2(s0), sf = unpack2(s1);
            float2 sg = unpack2(s2), so = unpack2(s3);
            float hc[2];
#pragma unroll
            for (int ci = 0; ci < 2; ci++) {
                float iv = (ci ? si.y : si.x) + (ci ? gpre[0].y : gpre[0].x);
                float fv = (ci ? sf.y : sf.x) + (ci ? gpre[1].y : gpre[1].x);
                float gg = (ci ? sg.y : sg.x) + (ci ? gpre[2].y : gpre[2].x);
                float ov = (ci ? so.y : so.x) + (ci ? gpre[3].y : gpre[3].x);
                float cprev = ci ? creg.y : creg.x;
                float cn = sigf(fv) * cprev + sigf(iv) * tanhf(gg);
                if (ci) creg.y = cn; else creg.x = cn;
                hc[ci] = sigf(ov) * tanhf(cn);
            }
            const int bglob = bglo + ob;
            *(float2*)&g_hrow[((size_t)l * 64 + bglob) * 1024 + dir * 512 + h0 + 2 * ohp] =
                make_float2(hc[0], hc[1]);
            float* hn = &g_h[p ^ 1][dir][0][0];
            hn[(h0 + 2 * ohp) * 64 + bglob]     = hc[0];
            hn[(h0 + 2 * ohp + 1) * 64 + bglob] = hc[1];
        }

        // ---- per-dir grid barrier (128 blocks per dir) ----
        if (t != 511) {
            __syncthreads();
            if (tid == 0) {
                bar_arrive(&g_bar[dir]);
                unsigned target = 128u * (unsigned)(t + 1);
                while (ld_acq(&g_bar[dir]) < target) { }
            }
            __syncthreads();
        }
    }
}

// ---------------- tag projection ---------------------------------------------
__global__ void __launch_bounds__(256) feats_kernel(const float* __restrict__ Wtag,
                                                    const float* __restrict__ btag) {
    int idx = blockIdx.x * 256 + threadIdx.x;   // 64*512*16
    int t = idx & 15;
    int l = (idx >> 4) & 511;
    int b = idx >> 13;
    const float4* hr = (const float4*)(g_hrow + (size_t)(l * 64 + b) * 1024);
    const float4* wr = (const float4*)(Wtag + (size_t)t * 1024);
    float a0 = 0.f, a1 = 0.f;
#pragma unroll 8
    for (int k = 0; k < 256; k += 2) {
        float4 x = hr[k],     w = wr[k];
        float4 y = hr[k + 1], v = wr[k + 1];
        a0 += x.x * w.x + x.y * w.y + x.z * w.z + x.w * w.w;
        a1 += y.x * v.x + y.y * v.y + y.z * v.z + y.w * v.w;
    }
    g_feats[((size_t)b * 512 + l) * 16 + t] = a0 + a1 + btag[t];
}

// ---------------- Viterbi -----------------------------------------------------
__global__ void __launch_bounds__(32) viterbi_kernel(const float* __restrict__ trans,
                                                     float* __restrict__ out) {
    int b = blockIdx.x;
    int lane = threadIdx.x;
    __shared__ unsigned char bp[512][16];
    __shared__ float smax[16];
    bool active = lane < 16;
    int row = active ? lane : 15;
    float tr[16];
#pragma unroll
    for (int j = 0; j < 16; j++) tr[j] = trans[row * 16 + j];
    float fv = (lane == 14) ? 0.0f : NEGV;   // START=14

    const float* fb = g_feats + (size_t)b * 512 * 16;
    for (int l = 0; l < 512; l++) {
        float best = -3.4e38f;
        int arg = 0;
#pragma unroll
        for (int j = 0; j < 16; j++) {
            float s = __shfl_sync(0xffffffffu, fv, j) + tr[j];
            if (s > best) { best = s; arg = j; }
        }
        float nf = best + fb[l * 16 + row];
        if (active) bp[l][lane] = (unsigned char)arg;
        fv = nf;
    }
    float term = fv + trans[15 * 16 + row];  // STOP=15
    if (active) smax[lane] = term;
    __syncwarp();
    if (lane == 0) {
        float best = smax[0]; int tag = 0;
        for (int j = 1; j < 16; j++) if (smax[j] > best) { best = smax[j]; tag = j; }
        out[b] = best;
        for (int l = 511; l >= 0; l--) {
            out[64 + b * 512 + l] = (float)tag;
            tag = bp[l][tag];
        }
    }
}

// ---------------- launch -------------------------------------------------------
extern "C" void kernel_launch(void* const* d_in, const int* in_sizes, int n_in,
                              void* d_out, int out_size) {
    const int*   sent  = (const int*)d_in[0];
    const float* embed = (const float*)d_in[1];
    const float* Wih_f = (const float*)d_in[2];
    const float* Whh_f = (const float*)d_in[3];
    const float* b_f   = (const float*)d_in[4];
    const float* Wih_b = (const float*)d_in[5];
    const float* Whh_b = (const float*)d_in[6];
    const float* b_b   = (const float*)d_in[7];
    const float* h0    = (const float*)d_in[8];
    const float* c0    = (const float*)d_in[9];
    const float* W_tag = (const float*)d_in[10];
    const float* b_tag = (const float*)d_in[11];
    const float* trans = (const float*)d_in[12];
    float* out = (float*)d_out;

    prepA<<<8448, 256>>>(Wih_f, Wih_b, h0);               // launch 1
    prepB<<<8192, 256>>>(Whh_f, Whh_b);                   // launch 2
    gemm1<<<dim3(32, 256), 256>>>(sent, embed, b_f, b_b); // launch 3
    lstm_persist<<<256, 256>>>(c0);                       // launch 4 (ncu slot)
    feats_kernel<<<2048, 256>>>(W_tag, b_tag);            // launch 5
    viterbi_kernel<<<64, 32>>>(trans, out);               // launch 6
}

// round 17
// speedup vs baseline: 1.5561x; 1.5561x over previous
#include <cuda_runtime.h>
#include <cuda_bf16.h>
#include <cstdint>

// BiLSTM-CRF forward, all fp32 (Viterbi argmax stability forbids low precision).
// R16 = R11 (best: 9894us) + three surgical fixes:
//  (1) padded conflict-free smem reduction (R11 publish was a 32-way bank
//      conflict: 256B lane stride), (2) weights in smem with one-iter software
//      pipeline (kills ldca load-to-use stall), (3) unchanged elsewhere.
//
// Shapes: V=50000 E=512 H=512 HD=1024 B=64 L=512 T=16, START=14 STOP=15

#define NEGV -10000.0f

typedef unsigned long long u64;

// smem layout (floats): Ws [0,16384) = 64KB ; red atoms after.
#define SMW_FLOATS 16384
#define RED_ATOMS  4672          // 8 * 584
#define SMEM_BYTES (SMW_FLOATS * 4 + RED_ATOMS * 16)

// ---------------- scratch (__device__ globals) ----------------------------
__device__ float g_G[(size_t)32768 * 4096];       // input-proj gates [l*64+b][dir*2048+g*512+h]
__device__ float g_Wt[(size_t)512 * 4096];        // Wih^T combined  [k][n]
__device__ float g_Whi[2][(size_t)64 * 512 * 32]; // Whh interleaved [dir][ht][k][hp][g][ci]
__device__ float g_h[2][2][512][64];              // [parity][dir][k][b]
__device__ float g_hrow[(size_t)32768 * 1024];    // [l*64+b][dir*512+h]
__device__ float g_feats[(size_t)64 * 512 * 16];  // [b][l][t]
__device__ unsigned g_bar[2];                     // per-dir step barrier

// ---------------- helpers ---------------------------------------------------
__device__ __forceinline__ void ffma2(u64 &d, u64 a, u64 b) {
    asm("fma.rn.f32x2 %0, %1, %2, %0;" : "+l"(d) : "l"(a), "l"(b));
}
__device__ __forceinline__ u64 addf2(u64 a, u64 b) {
    u64 r; asm("add.rn.f32x2 %0, %1, %2;" : "=l"(r) : "l"(a), "l"(b)); return r;
}
__device__ __forceinline__ u64 pack2(float x) {
    u64 r; asm("mov.b64 %0, {%1, %1};" : "=l"(r) : "f"(x)); return r;
}
__device__ __forceinline__ float2 unpack2(u64 v) {
    float2 f; asm("mov.b64 {%0, %1}, %2;" : "=f"(f.x), "=f"(f.y) : "l"(v)); return f;
}
__device__ __forceinline__ float sigf(float x) { return 1.0f / (1.0f + expf(-x)); }
__device__ __forceinline__ void cp16(unsigned dst_sm, const float* src) {
    asm volatile("cp.async.cg.shared.global [%0], [%1], 16;\n" :: "r"(dst_sm), "l"(src));
}
template <int N> __device__ __forceinline__ void cp_wait() {
    asm volatile("cp.async.wait_group %0;\n" :: "n"(N) : "memory");
}
__device__ __forceinline__ void cp_commit() {
    asm volatile("cp.async.commit_group;\n" ::: "memory");
}
__device__ __forceinline__ void bar_arrive(unsigned* p) {
    asm volatile("red.release.gpu.global.add.u32 [%0], %1;" :: "l"(p), "r"(1u) : "memory");
}
__device__ __forceinline__ unsigned ld_acq(const unsigned* p) {
    unsigned v; asm volatile("ld.acquire.gpu.global.u32 %0, [%1];" : "=r"(v) : "l"(p) : "memory");
    return v;
}

// ---------------- prep kernels ---------------------------------------------
__global__ void prepA(const float* __restrict__ wf, const float* __restrict__ wb,
                      const float* __restrict__ h0) {
    int idx = blockIdx.x * 256 + threadIdx.x;
    if (idx < 2) g_bar[idx] = 0;
    if (idx < 2097152) {                       // 512*4096
        int k = idx >> 12, n = idx & 4095;
        g_Wt[idx] = (n < 2048) ? wf[n * 512 + k] : wb[(n - 2048) * 512 + k];
    } else {
        int r2 = idx - 2097152;                // 2*512*64: h0 -> [k][b]
        if (r2 < 65536) {
            int dir = r2 >> 15; int r = r2 & 32767;
            int k = r >> 6, b = r & 63;
            g_h[0][dir][k][b] = h0[((size_t)dir * 64 + b) * 512 + k];
        }
    }
}
// Whh re-layout: [dir][ht][k][hp][g][ci], rows of 32 floats per (ht,k)
__global__ void prepB(const float* __restrict__ whf, const float* __restrict__ whb) {
    int idx = blockIdx.x * 256 + threadIdx.x;  // 2*64*512*32
    int dir = idx >> 20; int r = idx & ((1 << 20) - 1);
    int ht = r >> 14; int r2 = r & 16383;
    int k = r2 >> 5;  int c = r2 & 31;
    int hpq = c >> 3, g = (c >> 1) & 3, ci = c & 1;
    int n = g * 512 + ht * 8 + hpq * 2 + ci;
    const float* w = dir ? whb : whf;
    g_Whi[dir][r] = w[(size_t)n * 512 + k];
}

// ---------------- input projection GEMM (cp.async 2-stage, proven) ----------
__global__ void __launch_bounds__(256) gemm1(const int* __restrict__ sent,
                                             const float* __restrict__ embed,
                                             const float* __restrict__ bf,
                                             const float* __restrict__ bb) {
    __shared__ float As[2][128][16];
    __shared__ float Bs[2][16][128];
    __shared__ int toks[128];
    int tid = threadIdx.x;
    int n0 = blockIdx.x * 128;
    int m0 = blockIdx.y * 128;
    if (tid < 128) { int m = m0 + tid; toks[tid] = sent[(m & 63) * 512 + (m >> 6)]; }
    __syncthreads();
    int tx = tid & 15, ty = tid >> 4;
    unsigned smA = (unsigned)__cvta_generic_to_shared(&As[0][0][0]);
    unsigned smB = (unsigned)__cvta_generic_to_shared(&Bs[0][0][0]);

    u64 acc[8][4];
#pragma unroll
    for (int i = 0; i < 8; i++)
#pragma unroll
        for (int j = 0; j < 4; j++) acc[i][j] = 0ull;

    auto issue = [&](int k0, int buf) {
#pragma unroll
        for (int r = 0; r < 2; r++) {
            int idx = tid * 2 + r;
            int am = idx >> 2, aq = idx & 3;
            cp16(smA + (unsigned)(((buf * 128 + am) * 16 + aq * 4) * 4),
                 embed + (size_t)toks[am] * 512 + k0 + aq * 4);
            int bk = idx >> 5, bn = idx & 31;
            cp16(smB + (unsigned)(((buf * 16 + bk) * 128 + bn * 4) * 4),
                 g_Wt + (size_t)(k0 + bk) * 4096 + n0 + bn * 4);
        }
        cp_commit();
    };

    issue(0, 0);
    for (int c = 0; c < 32; c++) {
        cp_wait<0>();
        __syncthreads();
        if (c < 31) issue((c + 1) * 16, (c + 1) & 1);
        const int buf = c & 1;
#pragma unroll
        for (int k = 0; k < 16; k++) {
            u64 bv[4];
#pragma unroll
            for (int j = 0; j < 4; j++)
                bv[j] = *(const u64*)&Bs[buf][k][(j * 16 + tx) * 2];
#pragma unroll
            for (int i = 0; i < 8; i++) {
                u64 av = pack2(As[buf][ty * 8 + i][k]);
#pragma unroll
                for (int j = 0; j < 4; j++) ffma2(acc[i][j], av, bv[j]);
            }
        }
    }
#pragma unroll
    for (int j = 0; j < 4; j++) {
        int n = n0 + (j * 16 + tx) * 2;
        float2 bias;
        bias.x = (n < 2048) ? bf[n] : bb[n - 2048];
        bias.y = (n + 1 < 2048) ? bf[n + 1] : bb[n + 1 - 2048];
#pragma unroll
        for (int i = 0; i < 8; i++) {
            float2 v = unpack2(acc[i][j]);
            size_t row = (size_t)(m0 + ty * 8 + i);
            *(float2*)&g_G[row * 4096 + n] = make_float2(v.x + bias.x, v.y + bias.y);
        }
    }
}

// ---------------- persistent LSTM recurrence --------------------------------
// 128 blocks = 2 dirs x 64 h-tiles (8 h-cols). 256 threads = 8 warps; warp =
// k-eighth (64 k); lane = (bg 0..7, hp 0..3); thread = 8 b x 1 h-pair.
// Weights smem (pipelined LDS), h coalesced ldcg ring-4, padded conflict-free
// smem reduction (writer & reader both at the 4-wavefront floor).
__global__ void __launch_bounds__(256, 1) lstm_persist(const float* __restrict__ c0) {
    extern __shared__ float smf[];
    float* Ws = smf;                                  // [512][32] interleaved
    ulonglong2* red = (ulonglong2*)(smf + SMW_FLOATS);
    const int tid  = threadIdx.x;
    const int lane = tid & 31;
    const int kq   = tid >> 5;        // k-eighth 0..7
    const int bg   = lane >> 2;       // 0..7 (b-group of 8)
    const int hp   = lane & 3;        // 0..3 (h-pair)
    const int dir  = blockIdx.x >> 6;
    const int ht   = blockIdx.x & 63;
    const int h0   = ht * 8;
    const int ob = tid >> 2, ohp = tid & 3;   // epilogue owner cell

    // load weight slice into smem (16384 floats, float4 copies)
    {
        const float4* src = (const float4*)(g_Whi[dir] + (size_t)ht * 512 * 32);
        float4* dst = (float4*)Ws;
        for (int i = tid; i < 4096; i += 256) dst[i] = src[i];
    }
    // publish base: phys = kq*584 + bg*73 + bs*9 + hp*2 + gp
    const int wbase = kq * 584 + bg * 73 + hp * 2;
    // reduce base: phys = k8*584 + ob*9 + (ob>>3) + ohp*2 + gp
    const int rbase = ob * 9 + (ob >> 3) + ohp * 2;

    float2 creg = *(const float2*)&c0[((size_t)dir * 64 + ob) * 512 + h0 + 2 * ohp];
    __syncthreads();

    for (int t = 0; t < 512; t++) {
        const int p = t & 1;
        const int l = dir ? (511 - t) : t;

        // owners: G prefetch into registers (consumed post-reduction)
        float2 gpre[4];
        {
            const float* Gp = g_G + ((size_t)l * 64 + ob) * 4096
                            + (size_t)dir * 2048 + h0 + 2 * ohp;
#pragma unroll
            for (int g = 0; g < 4; g++) gpre[g] = __ldcg((const float2*)(Gp + g * 512));
        }

        const float* hb = &g_h[p][dir][kq * 64][bg * 8];   // row stride 64 floats

        u64 acc[8][4];
#pragma unroll
        for (int b = 0; b < 8; b++)
#pragma unroll
            for (int g = 0; g < 4; g++) acc[b][g] = 0ull;

        // h register ring, depth 4
        float4 hv[4][2];
#pragma unroll
        for (int i = 0; i < 4; i++) {
            hv[i][0] = __ldcg((const float4*)(hb + i * 64));
            hv[i][1] = __ldcg((const float4*)(hb + i * 64 + 4));
        }
        // weight software pipeline: one iteration ahead
        const float* wrow0 = Ws + (kq * 64) * 32 + hp * 8;
        ulonglong2 wA = *(const ulonglong2*)(wrow0);
        ulonglong2 wB = *(const ulonglong2*)(wrow0 + 4);

#pragma unroll 4
        for (int kk = 0; kk < 64; kk++) {
            float4 ha = hv[kk & 3][0], hbv = hv[kk & 3][1];
            if (kk + 4 < 64) {
                hv[kk & 3][0] = __ldcg((const float4*)(hb + (kk + 4) * 64));
                hv[kk & 3][1] = __ldcg((const float4*)(hb + (kk + 4) * 64 + 4));
            }
            ulonglong2 wAc = wA, wBc = wB;
            if (kk + 1 < 64) {
                const float* wrow = Ws + (kq * 64 + kk + 1) * 32 + hp * 8;
                wA = *(const ulonglong2*)(wrow);
                wB = *(const ulonglong2*)(wrow + 4);
            }
            float hs[8] = {ha.x, ha.y, ha.z, ha.w, hbv.x, hbv.y, hbv.z, hbv.w};
#pragma unroll
            for (int b = 0; b < 8; b++) {
                u64 a = pack2(hs[b]);
                ffma2(acc[b][0], a, wAc.x);
                ffma2(acc[b][1], a, wAc.y);
                ffma2(acc[b][2], a, wBc.x);
                ffma2(acc[b][3], a, wBc.y);
            }
        }

        // ---- publish partials (padded, conflict-free) ----
#pragma unroll
        for (int bs = 0; bs < 8; bs++) {
            red[wbase + bs * 9]     = make_ulonglong2(acc[bs][0], acc[bs][1]);
            red[wbase + bs * 9 + 1] = make_ulonglong2(acc[bs][2], acc[bs][3]);
        }
        __syncthreads();

        // ---- owners: reduce 8 k-eighths + fused LSTM pointwise ----
        {
            u64 s0 = 0ull, s1 = 0ull, s2 = 0ull, s3 = 0ull;
#pragma unroll
            for (int k8 = 0; k8 < 8; k8++) {
                ulonglong2 q0 = red[k8 * 584 + rbase];
                ulonglong2 q1 = red[k8 * 584 + rbase + 1];
                s0 = addf2(s0, q0.x); s1 = addf2(s1, q0.y);
                s2 = addf2(s2, q1.x); s3 = addf2(s3, q1.y);
            }
            float2 si = unpack2(s0), sf = unpack2(s1);
            float2 sg = unpack2(s2), so = unpack2(s3);
            float hc[2];
#pragma unroll
            for (int ci = 0; ci < 2; ci++) {
                float iv = (ci ? si.y : si.x) + (ci ? gpre[0].y : gpre[0].x);
                float fv = (ci ? sf.y : sf.x) + (ci ? gpre[1].y : gpre[1].x);
                float gg = (ci ? sg.y : sg.x) + (ci ? gpre[2].y : gpre[2].x);
                float ov = (ci ? so.y : so.x) + (ci ? gpre[3].y : gpre[3].x);
                float cprev = ci ? creg.y : creg.x;
                float cn = sigf(fv) * cprev + sigf(iv) * tanhf(gg);
                if (ci) creg.y = cn; else creg.x = cn;
                hc[ci] = sigf(ov) * tanhf(cn);
            }
            *(float2*)&g_hrow[((size_t)l * 64 + ob) * 1024 + dir * 512 + h0 + 2 * ohp] =
                make_float2(hc[0], hc[1]);
            float* hn = &g_h[p ^ 1][dir][0][0];
            hn[(h0 + 2 * ohp) * 64 + ob]     = hc[0];
            hn[(h0 + 2 * ohp + 1) * 64 + ob] = hc[1];
        }

        // ---- per-dir grid barrier ----
        if (t != 511) {
            __syncthreads();
            if (tid == 0) {
                bar_arrive(&g_bar[dir]);
                unsigned target = 64u * (unsigned)(t + 1);
                while (ld_acq(&g_bar[dir]) < target) { }
            }
            __syncthreads();
        }
    }
}

// ---------------- tag projection ---------------------------------------------
__global__ void __launch_bounds__(256) feats_kernel(const float* __restrict__ Wtag,
                                                    const float* __restrict__ btag) {
    int idx = blockIdx.x * 256 + threadIdx.x;   // 64*512*16
    int t = idx & 15;
    int l = (idx >> 4) & 511;
    int b = idx >> 13;
    const float4* hr = (const float4*)(g_hrow + (size_t)(l * 64 + b) * 1024);
    const float4* wr = (const float4*)(Wtag + (size_t)t * 1024);
    float a0 = 0.f, a1 = 0.f;
#pragma unroll 8
    for (int k = 0; k < 256; k += 2) {
        float4 x = hr[k],     w = wr[k];
        float4 y = hr[k + 1], v = wr[k + 1];
        a0 += x.x * w.x + x.y * w.y + x.z * w.z + x.w * w.w;
        a1 += y.x * v.x + y.y * v.y + y.z * v.z + y.w * v.w;
    }
    g_feats[((size_t)b * 512 + l) * 16 + t] = a0 + a1 + btag[t];
}

// ---------------- Viterbi -----------------------------------------------------
__global__ void __launch_bounds__(32) viterbi_kernel(const float* __restrict__ trans,
                                                     float* __restrict__ out) {
    int b = blockIdx.x;
    int lane = threadIdx.x;
    __shared__ unsigned char bp[512][16];
    __shared__ float smax[16];
    bool active = lane < 16;
    int row = active ? lane : 15;
    float tr[16];
#pragma unroll
    for (int j = 0; j < 16; j++) tr[j] = trans[row * 16 + j];
    float fv = (lane == 14) ? 0.0f : NEGV;   // START=14

    const float* fb = g_feats + (size_t)b * 512 * 16;
    for (int l = 0; l < 512; l++) {
        float best = -3.4e38f;
        int arg = 0;
#pragma unroll
        for (int j = 0; j < 16; j++) {
            float s = __shfl_sync(0xffffffffu, fv, j) + tr[j];
            if (s > best) { best = s; arg = j; }
        }
        float nf = best + fb[l * 16 + row];
        if (active) bp[l][lane] = (unsigned char)arg;
        fv = nf;
    }
    float term = fv + trans[15 * 16 + row];  // STOP=15
    if (active) smax[lane] = term;
    __syncwarp();
    if (lane == 0) {
        float best = smax[0]; int tag = 0;
        for (int j = 1; j < 16; j++) if (smax[j] > best) { best = smax[j]; tag = j; }
        out[b] = best;
        for (int l = 511; l >= 0; l--) {
            out[64 + b * 512 + l] = (float)tag;
            tag = bp[l][tag];
        }
    }
}

// ---------------- launch -------------------------------------------------------
extern "C" void kernel_launch(void* const* d_in, const int* in_sizes, int n_in,
                              void* d_out, int out_size) {
    const int*   sent  = (const int*)d_in[0];
    const float* embed = (const float*)d_in[1];
    const float* Wih_f = (const float*)d_in[2];
    const float* Whh_f = (const float*)d_in[3];
    const float* b_f   = (const float*)d_in[4];
    const float* Wih_b = (const float*)d_in[5];
    const float* Whh_b = (const float*)d_in[6];
    const float* b_b   = (const float*)d_in[7];
    const float* h0    = (const float*)d_in[8];
    const float* c0    = (const float*)d_in[9];
    const float* W_tag = (const float*)d_in[10];
    const float* b_tag = (const float*)d_in[11];
    const float* trans = (const float*)d_in[12];
    float* out = (float*)d_out;

    cudaFuncSetAttribute(lstm_persist, cudaFuncAttributeMaxDynamicSharedMemorySize, SMEM_BYTES);

    prepA<<<8448, 256>>>(Wih_f, Wih_b, h0);               // launch 1
    prepB<<<8192, 256>>>(Whh_f, Whh_b);                   // launch 2
    gemm1<<<dim3(32, 256), 256>>>(sent, embed, b_f, b_b); // launch 3
    lstm_persist<<<128, 256, SMEM_BYTES>>>(c0);           // launch 4 (ncu slot)
    feats_kernel<<<2048, 256>>>(W_tag, b_tag);            // launch 5
    viterbi_kernel<<<64, 32>>>(trans, out);               // launch 6
}